// round 4
// baseline (speedup 1.0000x reference)
#include <cuda_runtime.h>
#include <cstdint>

// out[src] += feat[dst] * w    ; feat [N,64] f32, E=1e6, N=1e5
// CSR-by-src built per call (hist + 3-stage scan + scatter), then atomic-free
// per-node accumulation (16 lanes/node, float4 gather + FMA, single store).
//
// Inputs: d_in[0]=feat f32[N*64], d_in[1]=ew f32[E],
//         d_in[2]=esrc i32[E],    d_in[3]=edst i32[E]

#define MAXN 100000
#define MAXE 1000000
#define SCAN_CHUNK 1024
#define MAXNB 128   // ceil(MAXN/1024) = 98

// g_cnt must be zero at entry of every call; k_accum re-zeroes it after use.
// (CUDA zero-initializes __device__ globals, so call 0 sees zeros too.)
__device__ int    g_cnt[MAXN];
__device__ int    g_start[MAXN];
__device__ int    g_cursor[MAXN];
__device__ float2 g_edge[MAXE];    // .x = __int_as_float(dst), .y = w
__device__ int    g_bsum[MAXNB];
__device__ int    g_boff[MAXNB];

__global__ void k_hist(const int4* __restrict__ esrc4, int n_edges4) {
    int i = blockIdx.x * blockDim.x + threadIdx.x;
    if (i < n_edges4) {
        int4 s = __ldg(&esrc4[i]);
        atomicAdd(&g_cnt[s.x], 1);
        atomicAdd(&g_cnt[s.y], 1);
        atomicAdd(&g_cnt[s.z], 1);
        atomicAdd(&g_cnt[s.w], 1);
    }
}

// one block per SCAN_CHUNK of nodes: chunk sum of counts
__global__ void k_bsum(int n) {
    __shared__ int sh[256];
    int b = blockIdx.x, t = threadIdx.x;
    int base = b * SCAN_CHUNK;
    int v = 0;
    for (int k = t; k < SCAN_CHUNK; k += 256) {
        int i = base + k;
        if (i < n) v += g_cnt[i];
    }
    sh[t] = v; __syncthreads();
    for (int off = 128; off > 0; off >>= 1) {
        if (t < off) sh[t] += sh[t + off];
        __syncthreads();
    }
    if (t == 0) g_bsum[b] = sh[0];
}

// exclusive scan of <=128 chunk sums, single block of 128 threads
__global__ void k_scanb(int nb) {
    __shared__ int s[128];
    int t = threadIdx.x;
    int v = (t < nb) ? g_bsum[t] : 0;
    s[t] = v; __syncthreads();
    for (int off = 1; off < 128; off <<= 1) {
        int x = (t >= off) ? s[t - off] : 0;
        __syncthreads();
        s[t] += x;
        __syncthreads();
    }
    if (t < nb) g_boff[t] = s[t] - v;   // exclusive
}

// per-chunk exclusive scan via warp shuffles -> g_start / g_cursor
__global__ __launch_bounds__(SCAN_CHUNK) void k_offsets(int n) {
    __shared__ int warp_sum[32];
    int b = blockIdx.x, t = threadIdx.x;
    int lane = t & 31, w = t >> 5;
    int i = b * SCAN_CHUNK + t;
    int v = (i < n) ? g_cnt[i] : 0;

    // inclusive warp scan
    int x = v;
    #pragma unroll
    for (int off = 1; off < 32; off <<= 1) {
        int y = __shfl_up_sync(0xffffffff, x, off);
        if (lane >= off) x += y;
    }
    if (lane == 31) warp_sum[w] = x;
    __syncthreads();

    if (w == 0) {
        int ws = warp_sum[lane];
        int z = ws;
        #pragma unroll
        for (int off = 1; off < 32; off <<= 1) {
            int y = __shfl_up_sync(0xffffffff, z, off);
            if (lane >= off) z += y;
        }
        warp_sum[lane] = z - ws;    // exclusive warp offsets
    }
    __syncthreads();

    if (i < n) {
        int start = g_boff[b] + warp_sum[w] + (x - v);  // exclusive within chunk
        g_start[i]  = start;
        g_cursor[i] = start;
    }
}

__global__ void k_scatter(const int* __restrict__ esrc,
                          const int* __restrict__ edst,
                          const float* __restrict__ ew,
                          int n_edges) {
    int i = blockIdx.x * blockDim.x + threadIdx.x;
    if (i >= n_edges) return;
    int s = __ldg(&esrc[i]);
    int pos = atomicAdd(&g_cursor[s], 1);
    g_edge[pos] = make_float2(__int_as_float(__ldg(&edst[i])), __ldg(&ew[i]));
}

// 16 lanes per node: gather feat rows for the node's edge list, FMA, store once.
// Re-zeroes g_cnt[node] so the next call starts from a clean histogram.
__global__ __launch_bounds__(256) void k_accum(const float* __restrict__ feat,
                                               float* __restrict__ out,
                                               int n_nodes) {
    int gid  = blockIdx.x * blockDim.x + threadIdx.x;
    int node = gid >> 4;
    int lane = gid & 15;
    if (node >= n_nodes) return;

    int cnt = g_cnt[node];          // warp-uniform per 16-lane group (broadcast)
    int beg = g_start[node];
    int end = beg + cnt;
    if (lane == 0) g_cnt[node] = 0; // restore invariant for next call

    float4 acc = make_float4(0.f, 0.f, 0.f, 0.f);
    int j = beg;
    for (; j + 1 < end; j += 2) {
        float2 e0 = __ldg(&g_edge[j]);
        float2 e1 = __ldg(&g_edge[j + 1]);
        int d0 = __float_as_int(e0.x);
        int d1 = __float_as_int(e1.x);
        float4 v0 = __ldg(&reinterpret_cast<const float4*>(feat + (long long)d0 * 64)[lane]);
        float4 v1 = __ldg(&reinterpret_cast<const float4*>(feat + (long long)d1 * 64)[lane]);
        acc.x += v0.x * e0.y + v1.x * e1.y;
        acc.y += v0.y * e0.y + v1.y * e1.y;
        acc.z += v0.z * e0.y + v1.z * e1.y;
        acc.w += v0.w * e0.y + v1.w * e1.y;
    }
    if (j < end) {
        float2 e0 = __ldg(&g_edge[j]);
        int d0 = __float_as_int(e0.x);
        float4 v0 = __ldg(&reinterpret_cast<const float4*>(feat + (long long)d0 * 64)[lane]);
        acc.x += v0.x * e0.y;
        acc.y += v0.y * e0.y;
        acc.z += v0.z * e0.y;
        acc.w += v0.w * e0.y;
    }
    reinterpret_cast<float4*>(out + (long long)node * 64)[lane] = acc;
}

extern "C" void kernel_launch(void* const* d_in, const int* in_sizes, int n_in,
                              void* d_out, int out_size)
{
    const float* feat = (const float*)d_in[0];
    const float* ew   = (const float*)d_in[1];
    const int*   esrc = (const int*)d_in[2];
    const int*   edst = (const int*)d_in[3];
    float*       out  = (float*)d_out;

    int n_edges  = in_sizes[1];
    int n_nodes  = out_size / 64;
    int nb       = (n_nodes + SCAN_CHUNK - 1) / SCAN_CHUNK;
    int n_edges4 = n_edges / 4;   // E = 1e6, divisible by 4

    k_hist<<<(n_edges4 + 255) / 256, 256>>>((const int4*)esrc, n_edges4);
    k_bsum<<<nb, 256>>>(n_nodes);
    k_scanb<<<1, 128>>>(nb);
    k_offsets<<<nb, SCAN_CHUNK>>>(n_nodes);
    k_scatter<<<(n_edges + 255) / 256, 256>>>(esrc, edst, ew, n_edges);

    long long total = (long long)n_nodes * 16;
    k_accum<<<(int)((total + 255) / 256), 256>>>(feat, out, n_nodes);
}

// round 5
// speedup vs baseline: 1.2933x; 1.2933x over previous
#include <cuda_runtime.h>
#include <cstdint>

// out[src] += feat[dst] * w    ; feat [N,64] f32, E=1e6, N=1e5
// 4-launch CSR pipeline:
//   k_hist      : degree histogram (atomics), also resets scan flags
//   k_scan      : fused chunk-scan + cross-chunk decoupled prefix (all-resident)
//   k_scatter   : permute (dst,w) into CSR order via cursor atomics
//   k_accum     : atomic-free per-node accumulation, 16 lanes/node
//
// Inputs: d_in[0]=feat f32[N*64], d_in[1]=ew f32[E],
//         d_in[2]=esrc i32[E],    d_in[3]=edst i32[E]

#define MAXN 100000
#define MAXE 1000000
#define SCAN_CHUNK 1024
#define MAXNB 128   // ceil(MAXN/1024) = 98

// g_cnt zero at entry of each call: zero-init at load; k_scan re-zeroes inline.
__device__ int    g_cnt[MAXN];
__device__ int    g_start[MAXN + 1];
__device__ int    g_cursor[MAXN];
__device__ float2 g_edge[MAXE];          // .x = __int_as_float(dst), .y = w
__device__ volatile int g_agg[MAXNB];
__device__ volatile int g_flag[MAXNB];   // reset by k_hist each call

__global__ void k_hist(const int4* __restrict__ esrc4, int n_edges4) {
    int i = blockIdx.x * blockDim.x + threadIdx.x;
    if (i < MAXNB) g_flag[i] = 0;        // reset scan flags for this call
    if (i < n_edges4) {
        int4 s = __ldg(&esrc4[i]);
        atomicAdd(&g_cnt[s.x], 1);
        atomicAdd(&g_cnt[s.y], 1);
        atomicAdd(&g_cnt[s.z], 1);
        atomicAdd(&g_cnt[s.w], 1);
    }
}

// grid = nb (<=98, all blocks resident -> spin is deadlock-free), block = 1024.
// Per chunk: warp-shuffle exclusive scan; cross-chunk: publish aggregate with
// fenced flag, sum predecessors. Writes g_start/g_cursor, re-zeroes g_cnt,
// last element writes the g_start[n] sentinel.
__global__ __launch_bounds__(SCAN_CHUNK) void k_scan(int n) {
    __shared__ int warp_sum[32];
    __shared__ int s_pref;
    int b = blockIdx.x, t = threadIdx.x;
    int lane = t & 31, w = t >> 5;
    int i = b * SCAN_CHUNK + t;

    int v = 0;
    if (i < n) { v = g_cnt[i]; g_cnt[i] = 0; }   // consume + reset histogram

    // inclusive warp scan
    int x = v;
    #pragma unroll
    for (int off = 1; off < 32; off <<= 1) {
        int y = __shfl_up_sync(0xffffffff, x, off);
        if (lane >= off) x += y;
    }
    if (lane == 31) warp_sum[w] = x;
    if (t == 0) s_pref = 0;
    __syncthreads();

    if (w == 0) {
        int ws = warp_sum[lane];
        int z = ws;
        #pragma unroll
        for (int off = 1; off < 32; off <<= 1) {
            int y = __shfl_up_sync(0xffffffff, z, off);
            if (lane >= off) z += y;
        }
        warp_sum[lane] = z - ws;                 // exclusive warp offsets
        if (lane == 31) {                        // block aggregate = z of last warp
            g_agg[b] = z;
            __threadfence();
            g_flag[b] = 1;
        }
    }
    __syncthreads();

    // decoupled prefix: sum aggregates of all predecessor blocks
    if (t < b) {
        while (g_flag[t] == 0) { }
        atomicAdd(&s_pref, g_agg[t]);
    }
    __syncthreads();
    int P = s_pref;

    if (i < n) {
        int start = P + warp_sum[w] + (x - v);   // global exclusive prefix
        g_start[i]  = start;
        g_cursor[i] = start;
        if (i == n - 1) g_start[n] = start + v;  // sentinel = total edges
    }
}

__global__ void k_scatter(const int* __restrict__ esrc,
                          const int* __restrict__ edst,
                          const float* __restrict__ ew,
                          int n_edges) {
    int i = blockIdx.x * blockDim.x + threadIdx.x;
    if (i >= n_edges) return;
    int s = __ldg(&esrc[i]);
    int pos = atomicAdd(&g_cursor[s], 1);
    g_edge[pos] = make_float2(__int_as_float(__ldg(&edst[i])), __ldg(&ew[i]));
}

// 16 lanes per node: gather feat rows along the node's CSR range, FMA, 1 store.
__global__ __launch_bounds__(256) void k_accum(const float* __restrict__ feat,
                                               float* __restrict__ out,
                                               int n_nodes) {
    int gid  = blockIdx.x * blockDim.x + threadIdx.x;
    int node = gid >> 4;
    int lane = gid & 15;
    if (node >= n_nodes) return;

    int beg = __ldg(&g_start[node]);
    int end = __ldg(&g_start[node + 1]);

    float4 acc = make_float4(0.f, 0.f, 0.f, 0.f);
    int j = beg;
    for (; j + 1 < end; j += 2) {
        float2 e0 = __ldg(&g_edge[j]);
        float2 e1 = __ldg(&g_edge[j + 1]);
        int d0 = __float_as_int(e0.x);
        int d1 = __float_as_int(e1.x);
        float4 v0 = __ldg(&reinterpret_cast<const float4*>(feat + (long long)d0 * 64)[lane]);
        float4 v1 = __ldg(&reinterpret_cast<const float4*>(feat + (long long)d1 * 64)[lane]);
        acc.x += v0.x * e0.y + v1.x * e1.y;
        acc.y += v0.y * e0.y + v1.y * e1.y;
        acc.z += v0.z * e0.y + v1.z * e1.y;
        acc.w += v0.w * e0.y + v1.w * e1.y;
    }
    if (j < end) {
        float2 e0 = __ldg(&g_edge[j]);
        int d0 = __float_as_int(e0.x);
        float4 v0 = __ldg(&reinterpret_cast<const float4*>(feat + (long long)d0 * 64)[lane]);
        acc.x += v0.x * e0.y;
        acc.y += v0.y * e0.y;
        acc.z += v0.z * e0.y;
        acc.w += v0.w * e0.y;
    }
    reinterpret_cast<float4*>(out + (long long)node * 64)[lane] = acc;
}

extern "C" void kernel_launch(void* const* d_in, const int* in_sizes, int n_in,
                              void* d_out, int out_size)
{
    const float* feat = (const float*)d_in[0];
    const float* ew   = (const float*)d_in[1];
    const int*   esrc = (const int*)d_in[2];
    const int*   edst = (const int*)d_in[3];
    float*       out  = (float*)d_out;

    int n_edges  = in_sizes[1];
    int n_nodes  = out_size / 64;
    int nb       = (n_nodes + SCAN_CHUNK - 1) / SCAN_CHUNK;   // 98
    int n_edges4 = n_edges / 4;

    k_hist<<<(n_edges4 + 255) / 256, 256>>>((const int4*)esrc, n_edges4);
    k_scan<<<nb, SCAN_CHUNK>>>(n_nodes);
    k_scatter<<<(n_edges + 255) / 256, 256>>>(esrc, edst, ew, n_edges);

    long long total = (long long)n_nodes * 16;
    k_accum<<<(int)((total + 255) / 256), 256>>>(feat, out, n_nodes);
}